// round 1
// baseline (speedup 1.0000x reference)
#include <cuda_runtime.h>
#include <math.h>

#define N_Y   100000
#define N_X   20000
#define KNN   16
#define NE    (N_X * KNN)      // 320000 edges
#define DEMB  192
#define HID   256
#define CIN   64

// Scratch (device globals: allocation-free contract)
__device__ float g_Ay[(size_t)N_Y * HID];   // y_e @ W1a                 [100000,256]
__device__ float g_Bx[(size_t)N_X * HID];   // x_e @ W1b + b1            [20000,256]
__device__ float g_H1[(size_t)NE  * HID];   // gelu(Ay[nbr]+Bx[q])       [320000,256]
__device__ float g_H2[(size_t)NE  * HID];   // gelu(H1@W2 + b2)          [320000,256]

__device__ __forceinline__ float gelu_f(float v) {
    return 0.5f * v * (1.0f + erff(v * 0.70710678118654752f));
}

// ---------------------------------------------------------------------------
// Kernel 1/2: sinusoidal embedding (computed on the fly in smem) followed by
// a [32,192]x[192,256] GEMM tile.  which==0 -> g_Ay, which==1 -> g_Bx.
// BM=32, BN=256, BK=16, 256 threads, per-thread 4x8 register tile.
// ---------------------------------------------------------------------------
__global__ void __launch_bounds__(256) embed_gemm_kernel(
    const float* __restrict__ pts,   // [n,3]
    const float* __restrict__ W,     // [192,256] row-major (slice of W1)
    const float* __restrict__ bias,  // [256] or nullptr
    int which)
{
    __shared__ float s_emb[32 * 193];   // padded rows (gcd(193,32)=1)
    __shared__ float s_B[16 * 256];
    __shared__ float s_freq[32];

    float* dst = which ? g_Bx : g_Ay;
    const int tid  = threadIdx.x;
    const int row0 = blockIdx.x * 32;

    if (tid < 32) s_freq[tid] = powf(10000.0f, -(float)tid / 32.0f);
    __syncthreads();

    // build embeddings for 32 rows: e = c*64 + f*2 + s  (s: 0=sin, 1=cos)
    for (int idx = tid; idx < 32 * 192; idx += 256) {
        int r = idx / 192, e = idx - r * 192;
        int c = e >> 6, f = (e & 63) >> 1, s = e & 1;
        float ang = pts[(row0 + r) * 3 + c] * s_freq[f];
        s_emb[r * 193 + e] = s ? cosf(ang) : sinf(ang);
    }
    __syncthreads();

    const int ty = tid >> 5, tx = tid & 31;   // rows ty*4.., cols tx*8..
    float acc[4][8];
#pragma unroll
    for (int i = 0; i < 4; i++)
#pragma unroll
        for (int j = 0; j < 8; j++) acc[i][j] = 0.f;

    for (int k0 = 0; k0 < 192; k0 += 16) {
        {   // stage B chunk [16,256]
            int kk = tid >> 4, cb = (tid & 15) * 16;
            const float4* g = (const float4*)(W + (k0 + kk) * 256 + cb);
            float4* sh = (float4*)(s_B + kk * 256 + cb);
            sh[0] = g[0]; sh[1] = g[1]; sh[2] = g[2]; sh[3] = g[3];
        }
        __syncthreads();
#pragma unroll
        for (int kk = 0; kk < 16; kk++) {
            float a_[4];
#pragma unroll
            for (int i = 0; i < 4; i++) a_[i] = s_emb[(ty * 4 + i) * 193 + k0 + kk];
            const float4* bv = (const float4*)(s_B + kk * 256 + tx * 8);
            float4 b0 = bv[0], b1 = bv[1];
            float b_[8] = {b0.x, b0.y, b0.z, b0.w, b1.x, b1.y, b1.z, b1.w};
#pragma unroll
            for (int i = 0; i < 4; i++)
#pragma unroll
                for (int j = 0; j < 8; j++) acc[i][j] = fmaf(a_[i], b_[j], acc[i][j]);
        }
        __syncthreads();
    }

#pragma unroll
    for (int i = 0; i < 4; i++) {
        int r = row0 + ty * 4 + i;
#pragma unroll
        for (int j = 0; j < 8; j += 4) {
            int col = tx * 8 + j;
            float4 v;
            v.x = acc[i][j + 0]; v.y = acc[i][j + 1];
            v.z = acc[i][j + 2]; v.w = acc[i][j + 3];
            if (bias) {
                v.x += bias[col + 0]; v.y += bias[col + 1];
                v.z += bias[col + 2]; v.w += bias[col + 3];
            }
            *(float4*)(dst + (size_t)r * 256 + col) = v;
        }
    }
}

// ---------------------------------------------------------------------------
// Kernel 3: H1[e,:] = gelu(Ay[nbr[e],:] + Bx[e>>4,:])   (elementwise, gather)
// one float4 per thread; grid*block == NE*64 exactly.
// ---------------------------------------------------------------------------
__global__ void __launch_bounds__(256) h1_kernel(const int* __restrict__ nbr)
{
    int idx = blockIdx.x * 256 + threadIdx.x;      // [0, NE*64)
    int e = idx >> 6;
    int c4 = (idx & 63) * 4;
    int nb = nbr[e];
    int q  = e >> 4;                               // uniform K=16 neighbors
    float4 a = *(const float4*)(g_Ay + (size_t)nb * 256 + c4);
    float4 b = *(const float4*)(g_Bx + (size_t)q  * 256 + c4);
    float4 h;
    h.x = gelu_f(a.x + b.x);
    h.y = gelu_f(a.y + b.y);
    h.z = gelu_f(a.z + b.z);
    h.w = gelu_f(a.w + b.w);
    *(float4*)(g_H1 + (size_t)e * 256 + c4) = h;
}

// ---------------------------------------------------------------------------
// Kernel 4: H2 = gelu(H1 @ W2 + b2)    [NE,256]x[256,256]
// BM=128, BN=256, BK=16, 512 threads, per-thread 8x8 register tile.
// ---------------------------------------------------------------------------
__global__ void __launch_bounds__(512) gemm2_kernel(
    const float* __restrict__ W2, const float* __restrict__ b2)
{
    __shared__ float sA[128 * 17];    // [128][16] padded
    __shared__ float sB[16 * 256];

    const int tid = threadIdx.x;
    const int e0  = blockIdx.x * 128;
    const int ty  = tid >> 5, tx = tid & 31;   // rows ty*8.., cols tx*8..

    float acc[8][8];
#pragma unroll
    for (int i = 0; i < 8; i++)
#pragma unroll
        for (int j = 0; j < 8; j++) acc[i][j] = 0.f;

    for (int k0 = 0; k0 < 256; k0 += 16) {
        {   // stage A chunk [128,16] from g_H1 (1 float4/thread)
            int r = tid >> 2, cb = (tid & 3) * 4;
            float4 v = *(const float4*)(g_H1 + (size_t)(e0 + r) * 256 + k0 + cb);
            float* d = sA + r * 17 + cb;
            d[0] = v.x; d[1] = v.y; d[2] = v.z; d[3] = v.w;
        }
        {   // stage B chunk [16,256] (2 float4/thread)
            int kk = tid >> 5, cb = (tid & 31) * 8;
            const float4* g = (const float4*)(W2 + (k0 + kk) * 256 + cb);
            float4* sh = (float4*)(sB + kk * 256 + cb);
            sh[0] = g[0]; sh[1] = g[1];
        }
        __syncthreads();
#pragma unroll
        for (int kk = 0; kk < 16; kk++) {
            float a_[8];
#pragma unroll
            for (int i = 0; i < 8; i++) a_[i] = sA[(ty * 8 + i) * 17 + kk];
            const float4* bv = (const float4*)(sB + kk * 256 + tx * 8);
            float4 b0 = bv[0], b1 = bv[1];
            float b_[8] = {b0.x, b0.y, b0.z, b0.w, b1.x, b1.y, b1.z, b1.w};
#pragma unroll
            for (int i = 0; i < 8; i++)
#pragma unroll
                for (int j = 0; j < 8; j++) acc[i][j] = fmaf(a_[i], b_[j], acc[i][j]);
        }
        __syncthreads();
    }

#pragma unroll
    for (int i = 0; i < 8; i++) {
        size_t base = (size_t)(e0 + ty * 8 + i) * 256 + tx * 8;
#pragma unroll
        for (int j = 0; j < 8; j += 4) {
            int col = tx * 8 + j;
            float4 v;
            v.x = gelu_f(acc[i][j + 0] + b2[col + 0]);
            v.y = gelu_f(acc[i][j + 1] + b2[col + 1]);
            v.z = gelu_f(acc[i][j + 2] + b2[col + 2]);
            v.w = gelu_f(acc[i][j + 3] + b2[col + 3]);
            *(float4*)(g_H2 + base + j) = v;
        }
    }
}

// ---------------------------------------------------------------------------
// Kernel 5: k_out = H2 @ W3 + b3; k_out *= f_y[nbr]; segment-sum over K=16.
// One block = 128 edges = 8 queries.  BM=128, BN=64, BK=16, 256 threads,
// per-thread 4x8 tile, smem staging for the K=16 reduction.
// ---------------------------------------------------------------------------
__global__ void __launch_bounds__(256) gemm3_out_kernel(
    const int*   __restrict__ nbr,
    const float* __restrict__ W3,
    const float* __restrict__ b3,
    const float* __restrict__ fy,
    float*       __restrict__ out)
{
    __shared__ float sA[128 * 17];
    __shared__ float sB[16 * 64];
    __shared__ float sRed[128 * 65];

    const int tid = threadIdx.x;
    const int e0  = blockIdx.x * 128;
    const int ty  = tid >> 3, tx = tid & 7;   // rows ty*4.., cols tx*8..

    float acc[4][8];
#pragma unroll
    for (int i = 0; i < 4; i++)
#pragma unroll
        for (int j = 0; j < 8; j++) acc[i][j] = 0.f;

    for (int k0 = 0; k0 < 256; k0 += 16) {
        {   // A chunk: 2 float4/thread
            int r = tid >> 1, cb = (tid & 1) * 8;
            const float4* g = (const float4*)(g_H2 + (size_t)(e0 + r) * 256 + k0 + cb);
            float4 v0 = g[0], v1 = g[1];
            float* d = sA + r * 17 + cb;
            d[0] = v0.x; d[1] = v0.y; d[2] = v0.z; d[3] = v0.w;
            d[4] = v1.x; d[5] = v1.y; d[6] = v1.z; d[7] = v1.w;
        }
        {   // B chunk [16,64]: 1 float4/thread
            int kk = tid >> 4, cb = (tid & 15) * 4;
            *(float4*)(sB + kk * 64 + cb) = *(const float4*)(W3 + (k0 + kk) * 64 + cb);
        }
        __syncthreads();
#pragma unroll
        for (int kk = 0; kk < 16; kk++) {
            float a_[4];
#pragma unroll
            for (int i = 0; i < 4; i++) a_[i] = sA[(ty * 4 + i) * 17 + kk];
            const float4* bv = (const float4*)(sB + kk * 64 + tx * 8);
            float4 b0 = bv[0], b1 = bv[1];
            float b_[8] = {b0.x, b0.y, b0.z, b0.w, b1.x, b1.y, b1.z, b1.w};
#pragma unroll
            for (int i = 0; i < 4; i++)
#pragma unroll
                for (int j = 0; j < 8; j++) acc[i][j] = fmaf(a_[i], b_[j], acc[i][j]);
        }
        __syncthreads();
    }

    // +b3, *f_y[nbr], stage for per-query reduction
#pragma unroll
    for (int i = 0; i < 4; i++) {
        int r  = ty * 4 + i;
        int nb = nbr[e0 + r];
        const float4* fv = (const float4*)(fy + (size_t)nb * 64 + tx * 8);
        float4 f0 = fv[0], f1 = fv[1];
        float f_[8] = {f0.x, f0.y, f0.z, f0.w, f1.x, f1.y, f1.z, f1.w};
#pragma unroll
        for (int j = 0; j < 8; j++) {
            int col = tx * 8 + j;
            sRed[r * 65 + col] = (acc[i][j] + b3[col]) * f_[j];
        }
    }
    __syncthreads();

    // 8 queries x 64 cols = 512 outputs; sum 16 edges each
    for (int o = tid; o < 512; o += 256) {
        int q = o >> 6, col = o & 63;
        float s = 0.f;
#pragma unroll
        for (int t = 0; t < 16; t++) s += sRed[(q * 16 + t) * 65 + col];
        out[(size_t)(blockIdx.x * 8 + q) * 64 + col] = s;
    }
}

// ---------------------------------------------------------------------------
extern "C" void kernel_launch(void* const* d_in, const int* in_sizes, int n_in,
                              void* d_out, int out_size)
{
    const float* y   = (const float*)d_in[0];
    const float* x   = (const float*)d_in[1];
    const float* f_y = (const float*)d_in[2];
    const int*   nbr = (const int*)d_in[3];
    // d_in[4] = neighbors_row_splits: uniform K=16 (arange*16) -> q = e>>4
    const float* W1  = (const float*)d_in[5];
    const float* b1  = (const float*)d_in[6];
    const float* W2  = (const float*)d_in[7];
    const float* b2  = (const float*)d_in[8];
    const float* W3  = (const float*)d_in[9];
    const float* b3  = (const float*)d_in[10];
    float* out = (float*)d_out;

    // 1) Ay = emb(y) @ W1[0:192,:]            (100000 rows, 32/block)
    embed_gemm_kernel<<<N_Y / 32, 256>>>(y, W1, nullptr, 0);
    // 2) Bx = emb(x) @ W1[192:384,:] + b1     (20000 rows)
    embed_gemm_kernel<<<N_X / 32, 256>>>(x, W1 + 192 * 256, b1, 1);
    // 3) H1 = gelu(Ay[nbr] + Bx[q])           (NE*64 float4 elements)
    h1_kernel<<<(NE * 64) / 256, 256>>>(nbr);
    // 4) H2 = gelu(H1 @ W2 + b2)
    gemm2_kernel<<<NE / 128, 512>>>(W2, b2);
    // 5) out = segsum((H2 @ W3 + b3) * f_y[nbr])
    gemm3_out_kernel<<<NE / 128, 256>>>(nbr, W3, b3, f_y, out);
}

// round 2
// speedup vs baseline: 1.5164x; 1.5164x over previous
#include <cuda_runtime.h>
#include <math.h>
#include <stdint.h>

#define N_Y   100000
#define N_X   20000
#define KNN   16
#define NE    (N_X * KNN)      // 320000 edges
#define HID   256
#define CIN   64

// Scratch (device globals: allocation-free contract)
__device__ float g_Ay[(size_t)N_Y * HID];   // y_e @ W1a              [100000,256]
__device__ float g_Bx[(size_t)N_X * HID];   // x_e @ W1b + b1         [20000,256]
__device__ float g_H2[(size_t)NE  * HID];   // gelu(H1@W2 + b2)       [320000,256]

__device__ __forceinline__ float gelu_f(float v) {
    return 0.5f * v * (1.0f + erff(v * 0.70710678118654752f));
}

__device__ __forceinline__ uint32_t f2tf32(float x) {
    uint32_t r;
    asm("cvt.rna.tf32.f32 %0, %1;" : "=r"(r) : "f"(x));
    return r;
}

// D += A(tf32) * B(tf32); m16n8k8, row.col, fp32 accum
__device__ __forceinline__ void mma_tf32(float* d, const uint32_t* a, const uint32_t* b) {
    asm volatile(
        "mma.sync.aligned.m16n8k8.row.col.f32.tf32.tf32.f32 "
        "{%0,%1,%2,%3}, {%4,%5,%6,%7}, {%8,%9}, {%0,%1,%2,%3};\n"
        : "+f"(d[0]), "+f"(d[1]), "+f"(d[2]), "+f"(d[3])
        : "r"(a[0]), "r"(a[1]), "r"(a[2]), "r"(a[3]), "r"(b[0]), "r"(b[1]));
}

// ---------------------------------------------------------------------------
// Kernel 1/2: sinusoidal embedding + [32,192]x[192,256] fp32 GEMM (unchanged)
// ---------------------------------------------------------------------------
__global__ void __launch_bounds__(256) embed_gemm_kernel(
    const float* __restrict__ pts,
    const float* __restrict__ W,
    const float* __restrict__ bias,
    int which)
{
    __shared__ float s_emb[32 * 193];
    __shared__ float s_B[16 * 256];
    __shared__ float s_freq[32];

    float* dst = which ? g_Bx : g_Ay;
    const int tid  = threadIdx.x;
    const int row0 = blockIdx.x * 32;

    if (tid < 32) s_freq[tid] = powf(10000.0f, -(float)tid / 32.0f);
    __syncthreads();

    for (int idx = tid; idx < 32 * 192; idx += 256) {
        int r = idx / 192, e = idx - r * 192;
        int c = e >> 6, f = (e & 63) >> 1, s = e & 1;
        float ang = pts[(row0 + r) * 3 + c] * s_freq[f];
        s_emb[r * 193 + e] = s ? cosf(ang) : sinf(ang);
    }
    __syncthreads();

    const int ty = tid >> 5, tx = tid & 31;
    float acc[4][8];
#pragma unroll
    for (int i = 0; i < 4; i++)
#pragma unroll
        for (int j = 0; j < 8; j++) acc[i][j] = 0.f;

    for (int k0 = 0; k0 < 192; k0 += 16) {
        {
            int kk = tid >> 4, cb = (tid & 15) * 16;
            const float4* g = (const float4*)(W + (k0 + kk) * 256 + cb);
            float4* sh = (float4*)(s_B + kk * 256 + cb);
            sh[0] = g[0]; sh[1] = g[1]; sh[2] = g[2]; sh[3] = g[3];
        }
        __syncthreads();
#pragma unroll
        for (int kk = 0; kk < 16; kk++) {
            float a_[4];
#pragma unroll
            for (int i = 0; i < 4; i++) a_[i] = s_emb[(ty * 4 + i) * 193 + k0 + kk];
            const float4* bv = (const float4*)(s_B + kk * 256 + tx * 8);
            float4 b0 = bv[0], b1 = bv[1];
            float b_[8] = {b0.x, b0.y, b0.z, b0.w, b1.x, b1.y, b1.z, b1.w};
#pragma unroll
            for (int i = 0; i < 4; i++)
#pragma unroll
                for (int j = 0; j < 8; j++) acc[i][j] = fmaf(a_[i], b_[j], acc[i][j]);
        }
        __syncthreads();
    }

#pragma unroll
    for (int i = 0; i < 4; i++) {
        int r = row0 + ty * 4 + i;
#pragma unroll
        for (int j = 0; j < 8; j += 4) {
            int col = tx * 8 + j;
            float4 v;
            v.x = acc[i][j + 0]; v.y = acc[i][j + 1];
            v.z = acc[i][j + 2]; v.w = acc[i][j + 3];
            if (bias) {
                v.x += bias[col + 0]; v.y += bias[col + 1];
                v.z += bias[col + 2]; v.w += bias[col + 3];
            }
            *(float4*)(dst + (size_t)r * 256 + col) = v;
        }
    }
}

// ---------------------------------------------------------------------------
// Kernel 3 (fused): H2 = gelu( gelu(Ay[nbr]+Bx[q]) @ W2 + b2 )
// tf32 mma. BM=128 edges, BN=256, BK=16. 512 threads = 16 warps (4x4);
// warp tile 32x64 = (2 x m16) x (8 x n8).
// ---------------------------------------------------------------------------
#define SA_P 17
#define SB_P 260
__global__ void __launch_bounds__(512) gemm2_mma_kernel(
    const int*   __restrict__ nbr,
    const float* __restrict__ W2,
    const float* __restrict__ b2)
{
    __shared__ uint32_t sA[128 * SA_P];    // [row][k] tf32, padded
    __shared__ uint32_t sB[16 * SB_P];     // [k][n]  tf32, padded
    __shared__ int s_nbr[128];

    const int tid  = threadIdx.x;
    const int e0   = blockIdx.x * 128;
    const int warp = tid >> 5, lane = tid & 31;
    const int wm = (warp & 3) * 32;        // warp row offset
    const int wn = (warp >> 2) * 64;       // warp col offset
    const int lr = lane >> 2, lc = lane & 3;

    if (tid < 128) s_nbr[tid] = nbr[e0 + tid];
    __syncthreads();

    float acc[2][8][4];
#pragma unroll
    for (int mi = 0; mi < 2; mi++)
#pragma unroll
        for (int ni = 0; ni < 8; ni++)
#pragma unroll
            for (int t = 0; t < 4; t++) acc[mi][ni][t] = 0.f;

    for (int k0 = 0; k0 < 256; k0 += 16) {
        {   // stage A: gather + add + gelu + cvt  (4 elems/thread)
            int r = tid >> 2, cb = (tid & 3) * 4;
            int nb = s_nbr[r];
            int q  = (e0 + r) >> 4;
            float4 a = *(const float4*)(g_Ay + (size_t)nb * 256 + k0 + cb);
            float4 b = *(const float4*)(g_Bx + (size_t)q  * 256 + k0 + cb);
            uint32_t* d = sA + r * SA_P + cb;
            d[0] = f2tf32(gelu_f(a.x + b.x));
            d[1] = f2tf32(gelu_f(a.y + b.y));
            d[2] = f2tf32(gelu_f(a.z + b.z));
            d[3] = f2tf32(gelu_f(a.w + b.w));
        }
        {   // stage B: [16][256] cvt  (8 elems/thread)
            int kk = tid >> 5, cb = (tid & 31) * 8;
            const float4* g = (const float4*)(W2 + (size_t)(k0 + kk) * 256 + cb);
            float4 v0 = g[0], v1 = g[1];
            uint32_t* d = sB + kk * SB_P + cb;
            d[0] = f2tf32(v0.x); d[1] = f2tf32(v0.y);
            d[2] = f2tf32(v0.z); d[3] = f2tf32(v0.w);
            d[4] = f2tf32(v1.x); d[5] = f2tf32(v1.y);
            d[6] = f2tf32(v1.z); d[7] = f2tf32(v1.w);
        }
        __syncthreads();

#pragma unroll
        for (int kk = 0; kk < 16; kk += 8) {
            uint32_t afr[2][4];
#pragma unroll
            for (int mi = 0; mi < 2; mi++) {
                int r = wm + mi * 16 + lr;
                afr[mi][0] = sA[r * SA_P + kk + lc];
                afr[mi][1] = sA[(r + 8) * SA_P + kk + lc];
                afr[mi][2] = sA[r * SA_P + kk + lc + 4];
                afr[mi][3] = sA[(r + 8) * SA_P + kk + lc + 4];
            }
            uint32_t bfr[8][2];
#pragma unroll
            for (int ni = 0; ni < 8; ni++) {
                int n = wn + ni * 8 + lr;
                bfr[ni][0] = sB[(kk + lc) * SB_P + n];
                bfr[ni][1] = sB[(kk + 4 + lc) * SB_P + n];
            }
#pragma unroll
            for (int mi = 0; mi < 2; mi++)
#pragma unroll
                for (int ni = 0; ni < 8; ni++)
                    mma_tf32(acc[mi][ni], afr[mi], bfr[ni]);
        }
        __syncthreads();
    }

    // epilogue: +b2, gelu, store
#pragma unroll
    for (int mi = 0; mi < 2; mi++) {
        int r0 = e0 + wm + mi * 16 + lr;
#pragma unroll
        for (int ni = 0; ni < 8; ni++) {
            int col = wn + ni * 8 + lc * 2;
            float bb0 = b2[col], bb1 = b2[col + 1];
            float2 v0, v1;
            v0.x = gelu_f(acc[mi][ni][0] + bb0);
            v0.y = gelu_f(acc[mi][ni][1] + bb1);
            v1.x = gelu_f(acc[mi][ni][2] + bb0);
            v1.y = gelu_f(acc[mi][ni][3] + bb1);
            *(float2*)(g_H2 + (size_t)r0 * 256 + col) = v0;
            *(float2*)(g_H2 + (size_t)(r0 + 8) * 256 + col) = v1;
        }
    }
}

// ---------------------------------------------------------------------------
// Kernel 4: out = segsum( (H2 @ W3 + b3) * f_y[nbr] )   tf32 mma
// BM=128 edges, BN=64, BK=16. 256 threads = 8 warps; warp = m16 x n64.
// ---------------------------------------------------------------------------
#define SB3_P 68
__global__ void __launch_bounds__(256) gemm3_mma_kernel(
    const int*   __restrict__ nbr,
    const float* __restrict__ W3,
    const float* __restrict__ b3,
    const float* __restrict__ fy,
    float*       __restrict__ out)
{
    __shared__ uint32_t sA[128 * SA_P];
    __shared__ uint32_t sB[16 * SB3_P];
    __shared__ float    sRed[128 * 65];
    __shared__ int s_nbr[128];

    const int tid  = threadIdx.x;
    const int e0   = blockIdx.x * 128;
    const int warp = tid >> 5, lane = tid & 31;
    const int lr = lane >> 2, lc = lane & 3;

    if (tid < 128) s_nbr[tid] = nbr[e0 + tid];
    __syncthreads();

    float acc[8][4];
#pragma unroll
    for (int ni = 0; ni < 8; ni++)
#pragma unroll
        for (int t = 0; t < 4; t++) acc[ni][t] = 0.f;

    for (int k0 = 0; k0 < 256; k0 += 16) {
        {   // stage A: [128][16] from g_H2, cvt (8 elems/thread)
            int r = tid >> 1, cb = (tid & 1) * 8;
            const float4* g = (const float4*)(g_H2 + (size_t)(e0 + r) * 256 + k0 + cb);
            float4 v0 = g[0], v1 = g[1];
            uint32_t* d = sA + r * SA_P + cb;
            d[0] = f2tf32(v0.x); d[1] = f2tf32(v0.y);
            d[2] = f2tf32(v0.z); d[3] = f2tf32(v0.w);
            d[4] = f2tf32(v1.x); d[5] = f2tf32(v1.y);
            d[6] = f2tf32(v1.z); d[7] = f2tf32(v1.w);
        }
        {   // stage B: [16][64] from W3, cvt (4 elems/thread)
            int kk = tid >> 4, cb = (tid & 15) * 4;
            float4 v = *(const float4*)(W3 + (size_t)(k0 + kk) * 64 + cb);
            uint32_t* d = sB + kk * SB3_P + cb;
            d[0] = f2tf32(v.x); d[1] = f2tf32(v.y);
            d[2] = f2tf32(v.z); d[3] = f2tf32(v.w);
        }
        __syncthreads();

#pragma unroll
        for (int kk = 0; kk < 16; kk += 8) {
            uint32_t afr[4];
            {
                int r = warp * 16 + lr;
                afr[0] = sA[r * SA_P + kk + lc];
                afr[1] = sA[(r + 8) * SA_P + kk + lc];
                afr[2] = sA[r * SA_P + kk + lc + 4];
                afr[3] = sA[(r + 8) * SA_P + kk + lc + 4];
            }
#pragma unroll
            for (int ni = 0; ni < 8; ni++) {
                uint32_t bfr[2];
                int n = ni * 8 + lr;
                bfr[0] = sB[(kk + lc) * SB3_P + n];
                bfr[1] = sB[(kk + 4 + lc) * SB3_P + n];
                mma_tf32(acc[ni], afr, bfr);
            }
        }
        __syncthreads();
    }

    // epilogue: +b3, *f_y[nbr], stage for per-query reduction
    {
        int r0 = warp * 16 + lr;       // local edge row
        int r1 = r0 + 8;
        int nb0 = s_nbr[r0], nb1 = s_nbr[r1];
#pragma unroll
        for (int ni = 0; ni < 8; ni++) {
            int col = ni * 8 + lc * 2;
            float bb0 = b3[col], bb1 = b3[col + 1];
            float2 f0 = *(const float2*)(fy + (size_t)nb0 * 64 + col);
            float2 f1 = *(const float2*)(fy + (size_t)nb1 * 64 + col);
            sRed[r0 * 65 + col]     = (acc[ni][0] + bb0) * f0.x;
            sRed[r0 * 65 + col + 1] = (acc[ni][1] + bb1) * f0.y;
            sRed[r1 * 65 + col]     = (acc[ni][2] + bb0) * f1.x;
            sRed[r1 * 65 + col + 1] = (acc[ni][3] + bb1) * f1.y;
        }
    }
    __syncthreads();

    // 8 queries x 64 cols; sum 16 edges each
    for (int o = tid; o < 512; o += 256) {
        int q = o >> 6, col = o & 63;
        float s = 0.f;
#pragma unroll
        for (int t = 0; t < 16; t++) s += sRed[(q * 16 + t) * 65 + col];
        out[(size_t)(blockIdx.x * 8 + q) * 64 + col] = s;
    }
}

// ---------------------------------------------------------------------------
extern "C" void kernel_launch(void* const* d_in, const int* in_sizes, int n_in,
                              void* d_out, int out_size)
{
    const float* y   = (const float*)d_in[0];
    const float* x   = (const float*)d_in[1];
    const float* f_y = (const float*)d_in[2];
    const int*   nbr = (const int*)d_in[3];
    // d_in[4] = neighbors_row_splits (uniform K=16 -> q = e>>4)
    const float* W1  = (const float*)d_in[5];
    const float* b1  = (const float*)d_in[6];
    const float* W2  = (const float*)d_in[7];
    const float* b2  = (const float*)d_in[8];
    const float* W3  = (const float*)d_in[9];
    const float* b3  = (const float*)d_in[10];
    float* out = (float*)d_out;

    embed_gemm_kernel<<<N_Y / 32, 256>>>(y, W1, nullptr, 0);
    embed_gemm_kernel<<<N_X / 32, 256>>>(x, W1 + 192 * 256, b1, 1);
    gemm2_mma_kernel<<<NE / 128, 512>>>(nbr, W2, b2);
    gemm3_mma_kernel<<<NE / 128, 256>>>(nbr, W3, b3, f_y, out);
}

// round 3
// speedup vs baseline: 2.4360x; 1.6064x over previous
#include <cuda_runtime.h>
#include <math.h>
#include <stdint.h>

#define N_Y   100000
#define N_X   20000
#define KNN   16
#define NE    (N_X * KNN)      // 320000 edges
#define HID   256
#define CIN   64

// Conflict-free paddings (banks: lc*PAD+lr all-distinct mod 32)
#define SA_P  20
#define SB_P  264
#define SB3_P 72

// Scratch (device globals: allocation-free contract)
__device__ float g_Ay[(size_t)N_Y * HID];
__device__ float g_Bx[(size_t)N_X * HID];
__device__ float g_H2[(size_t)NE  * HID];

__device__ __forceinline__ float gelu_f(float v) {
    return 0.5f * v * (1.0f + erff(v * 0.70710678118654752f));
}

__device__ __forceinline__ uint32_t f2tf32(float x) {
    uint32_t r;
    asm("cvt.rna.tf32.f32 %0, %1;" : "=r"(r) : "f"(x));
    return r;
}

__device__ __forceinline__ void mma_tf32(float* d, const uint32_t* a, const uint32_t* b) {
    asm volatile(
        "mma.sync.aligned.m16n8k8.row.col.f32.tf32.tf32.f32 "
        "{%0,%1,%2,%3}, {%4,%5,%6,%7}, {%8,%9}, {%0,%1,%2,%3};\n"
        : "+f"(d[0]), "+f"(d[1]), "+f"(d[2]), "+f"(d[3])
        : "r"(a[0]), "r"(a[1]), "r"(a[2]), "r"(a[3]), "r"(b[0]), "r"(b[1]));
}

// ---------------------------------------------------------------------------
// Embed + GEMM1 (tf32 mma): dst[r,:] = emb(pts[r,:]) @ W (+bias)
// BM=128 rows, BN=256, K=192.  512 threads = 16 warps (4x4), warp 32x64.
// ---------------------------------------------------------------------------
__global__ void __launch_bounds__(512) embed_mma_kernel(
    const float* __restrict__ pts,
    const float* __restrict__ W,     // [192,256] row-major
    const float* __restrict__ bias,  // may be null
    int which, int n)                // which: 0->g_Ay, 1->g_Bx
{
    __shared__ uint32_t sA[128 * SA_P];
    __shared__ uint32_t sB[16 * SB_P];
    __shared__ float s_pts[128 * 3];
    __shared__ float s_freq[32];

    float* dst = which ? g_Bx : g_Ay;
    const int tid  = threadIdx.x;
    const int row0 = blockIdx.x * 128;
    const int warp = tid >> 5, lane = tid & 31;
    const int wm = (warp & 3) * 32, wn = (warp >> 2) * 64;
    const int lr = lane >> 2, lc = lane & 3;

    if (tid < 32) s_freq[tid] = powf(10000.0f, -(float)tid / 32.0f);
    if (tid < 384) {
        int r = tid / 3, c = tid - r * 3;
        int row = row0 + r;
        s_pts[tid] = (row < n) ? pts[row * 3 + c] : 0.f;
    }
    __syncthreads();

    // per-thread staging coords
    const int ar = tid >> 2, acb = (tid & 3) * 4;      // A: 4 elems
    const int bk = tid >> 5, bcb = (tid & 31) * 8;     // B: 8 elems

    // compute A elems for chunk k0 into regs
    auto computeA = [&](int k0, float* av) {
#pragma unroll
        for (int j = 0; j < 4; j++) {
            int e = k0 + acb + j;
            int c = e >> 6, f = (e & 63) >> 1, s = e & 1;
            float ang = s_pts[ar * 3 + c] * s_freq[f];
            av[j] = s ? cosf(ang) : sinf(ang);
        }
    };

    float acc[2][8][4];
#pragma unroll
    for (int mi = 0; mi < 2; mi++)
#pragma unroll
        for (int ni = 0; ni < 8; ni++)
#pragma unroll
            for (int t = 0; t < 4; t++) acc[mi][ni][t] = 0.f;

    // prologue: stage chunk 0
    {
        float av[4];
        computeA(0, av);
        uint32_t* d = sA + ar * SA_P + acb;
        d[0] = f2tf32(av[0]); d[1] = f2tf32(av[1]);
        d[2] = f2tf32(av[2]); d[3] = f2tf32(av[3]);
        const float4* g = (const float4*)(W + (size_t)bk * 256 + bcb);
        float4 v0 = g[0], v1 = g[1];
        uint32_t* db = sB + bk * SB_P + bcb;
        db[0] = f2tf32(v0.x); db[1] = f2tf32(v0.y); db[2] = f2tf32(v0.z); db[3] = f2tf32(v0.w);
        db[4] = f2tf32(v1.x); db[5] = f2tf32(v1.y); db[6] = f2tf32(v1.z); db[7] = f2tf32(v1.w);
    }
    __syncthreads();

    for (int k0 = 0; k0 < 192; k0 += 16) {
        const bool nx = (k0 + 16) < 192;
        float av[4]; float4 wv0, wv1;
        if (nx) {
            computeA(k0 + 16, av);
            const float4* g = (const float4*)(W + (size_t)(k0 + 16 + bk) * 256 + bcb);
            wv0 = g[0]; wv1 = g[1];
        }
#pragma unroll
        for (int kk = 0; kk < 16; kk += 8) {
            uint32_t afr[2][4];
#pragma unroll
            for (int mi = 0; mi < 2; mi++) {
                int r = wm + mi * 16 + lr;
                afr[mi][0] = sA[r * SA_P + kk + lc];
                afr[mi][1] = sA[(r + 8) * SA_P + kk + lc];
                afr[mi][2] = sA[r * SA_P + kk + lc + 4];
                afr[mi][3] = sA[(r + 8) * SA_P + kk + lc + 4];
            }
            uint32_t bfr[8][2];
#pragma unroll
            for (int ni = 0; ni < 8; ni++) {
                int nn = wn + ni * 8 + lr;
                bfr[ni][0] = sB[(kk + lc) * SB_P + nn];
                bfr[ni][1] = sB[(kk + 4 + lc) * SB_P + nn];
            }
#pragma unroll
            for (int mi = 0; mi < 2; mi++)
#pragma unroll
                for (int ni = 0; ni < 8; ni++)
                    mma_tf32(acc[mi][ni], afr[mi], bfr[ni]);
        }
        __syncthreads();
        if (nx) {
            uint32_t* d = sA + ar * SA_P + acb;
            d[0] = f2tf32(av[0]); d[1] = f2tf32(av[1]);
            d[2] = f2tf32(av[2]); d[3] = f2tf32(av[3]);
            uint32_t* db = sB + bk * SB_P + bcb;
            db[0] = f2tf32(wv0.x); db[1] = f2tf32(wv0.y); db[2] = f2tf32(wv0.z); db[3] = f2tf32(wv0.w);
            db[4] = f2tf32(wv1.x); db[5] = f2tf32(wv1.y); db[6] = f2tf32(wv1.z); db[7] = f2tf32(wv1.w);
            __syncthreads();
        }
    }

    // epilogue: +bias, store fp32 (guarded)
#pragma unroll
    for (int mi = 0; mi < 2; mi++) {
        int r0 = row0 + wm + mi * 16 + lr;
        int r1 = r0 + 8;
#pragma unroll
        for (int ni = 0; ni < 8; ni++) {
            int col = wn + ni * 8 + lc * 2;
            float bb0 = bias ? bias[col]     : 0.f;
            float bb1 = bias ? bias[col + 1] : 0.f;
            if (r0 < n) {
                float2 v; v.x = acc[mi][ni][0] + bb0; v.y = acc[mi][ni][1] + bb1;
                *(float2*)(dst + (size_t)r0 * 256 + col) = v;
            }
            if (r1 < n) {
                float2 v; v.x = acc[mi][ni][2] + bb0; v.y = acc[mi][ni][3] + bb1;
                *(float2*)(dst + (size_t)r1 * 256 + col) = v;
            }
        }
    }
}

// ---------------------------------------------------------------------------
// GEMM2 (fused gather+gelu): H2 = gelu( gelu(Ay[nbr]+Bx[q]) @ W2 + b2 )
// BM=128 edges, BN=256, K=256. 512 threads, reg-prefetch pipeline.
// ---------------------------------------------------------------------------
__global__ void __launch_bounds__(512) gemm2_mma_kernel(
    const int*   __restrict__ nbr,
    const float* __restrict__ W2,
    const float* __restrict__ b2)
{
    __shared__ uint32_t sA[128 * SA_P];
    __shared__ uint32_t sB[16 * SB_P];
    __shared__ int s_nbr[128];

    const int tid  = threadIdx.x;
    const int e0   = blockIdx.x * 128;
    const int warp = tid >> 5, lane = tid & 31;
    const int wm = (warp & 3) * 32, wn = (warp >> 2) * 64;
    const int lr = lane >> 2, lc = lane & 3;

    if (tid < 128) s_nbr[tid] = nbr[e0 + tid];
    __syncthreads();

    // fixed per-thread staging pointers
    const int ar = tid >> 2, acb = (tid & 3) * 4;
    const int nb = s_nbr[ar];
    const int q  = (e0 + ar) >> 4;
    const float* pA = g_Ay + (size_t)nb * 256 + acb;
    const float* pB = g_Bx + (size_t)q  * 256 + acb;
    const int bk = tid >> 5, bcb = (tid & 31) * 8;

    float acc[2][8][4];
#pragma unroll
    for (int mi = 0; mi < 2; mi++)
#pragma unroll
        for (int ni = 0; ni < 8; ni++)
#pragma unroll
            for (int t = 0; t < 4; t++) acc[mi][ni][t] = 0.f;

    // prologue: stage chunk 0
    {
        float4 a = *(const float4*)(pA);
        float4 b = *(const float4*)(pB);
        uint32_t* d = sA + ar * SA_P + acb;
        d[0] = f2tf32(gelu_f(a.x + b.x));
        d[1] = f2tf32(gelu_f(a.y + b.y));
        d[2] = f2tf32(gelu_f(a.z + b.z));
        d[3] = f2tf32(gelu_f(a.w + b.w));
        const float4* g = (const float4*)(W2 + (size_t)bk * 256 + bcb);
        float4 v0 = g[0], v1 = g[1];
        uint32_t* db = sB + bk * SB_P + bcb;
        db[0] = f2tf32(v0.x); db[1] = f2tf32(v0.y); db[2] = f2tf32(v0.z); db[3] = f2tf32(v0.w);
        db[4] = f2tf32(v1.x); db[5] = f2tf32(v1.y); db[6] = f2tf32(v1.z); db[7] = f2tf32(v1.w);
    }
    __syncthreads();

    for (int k0 = 0; k0 < 256; k0 += 16) {
        const bool nx = (k0 + 16) < 256;
        float4 a, b, wv0, wv1;
        if (nx) {
            a = *(const float4*)(pA + k0 + 16);
            b = *(const float4*)(pB + k0 + 16);
            const float4* g = (const float4*)(W2 + (size_t)(k0 + 16 + bk) * 256 + bcb);
            wv0 = g[0]; wv1 = g[1];
        }
#pragma unroll
        for (int kk = 0; kk < 16; kk += 8) {
            uint32_t afr[2][4];
#pragma unroll
            for (int mi = 0; mi < 2; mi++) {
                int r = wm + mi * 16 + lr;
                afr[mi][0] = sA[r * SA_P + kk + lc];
                afr[mi][1] = sA[(r + 8) * SA_P + kk + lc];
                afr[mi][2] = sA[r * SA_P + kk + lc + 4];
                afr[mi][3] = sA[(r + 8) * SA_P + kk + lc + 4];
            }
            uint32_t bfr[8][2];
#pragma unroll
            for (int ni = 0; ni < 8; ni++) {
                int nn = wn + ni * 8 + lr;
                bfr[ni][0] = sB[(kk + lc) * SB_P + nn];
                bfr[ni][1] = sB[(kk + 4 + lc) * SB_P + nn];
            }
#pragma unroll
            for (int mi = 0; mi < 2; mi++)
#pragma unroll
                for (int ni = 0; ni < 8; ni++)
                    mma_tf32(acc[mi][ni], afr[mi], bfr[ni]);
        }
        __syncthreads();
        if (nx) {
            uint32_t* d = sA + ar * SA_P + acb;
            d[0] = f2tf32(gelu_f(a.x + b.x));
            d[1] = f2tf32(gelu_f(a.y + b.y));
            d[2] = f2tf32(gelu_f(a.z + b.z));
            d[3] = f2tf32(gelu_f(a.w + b.w));
            uint32_t* db = sB + bk * SB_P + bcb;
            db[0] = f2tf32(wv0.x); db[1] = f2tf32(wv0.y); db[2] = f2tf32(wv0.z); db[3] = f2tf32(wv0.w);
            db[4] = f2tf32(wv1.x); db[5] = f2tf32(wv1.y); db[6] = f2tf32(wv1.z); db[7] = f2tf32(wv1.w);
            __syncthreads();
        }
    }

    // epilogue: +b2, gelu, store
#pragma unroll
    for (int mi = 0; mi < 2; mi++) {
        int r0 = e0 + wm + mi * 16 + lr;
#pragma unroll
        for (int ni = 0; ni < 8; ni++) {
            int col = wn + ni * 8 + lc * 2;
            float bb0 = b2[col], bb1 = b2[col + 1];
            float2 v0, v1;
            v0.x = gelu_f(acc[mi][ni][0] + bb0);
            v0.y = gelu_f(acc[mi][ni][1] + bb1);
            v1.x = gelu_f(acc[mi][ni][2] + bb0);
            v1.y = gelu_f(acc[mi][ni][3] + bb1);
            *(float2*)(g_H2 + (size_t)r0 * 256 + col) = v0;
            *(float2*)(g_H2 + (size_t)(r0 + 8) * 256 + col) = v1;
        }
    }
}

// ---------------------------------------------------------------------------
// GEMM3 + segsum: out = segsum( (H2 @ W3 + b3) * f_y[nbr] )
// BM=128 edges, BN=64, K=256. 256 threads = 8 warps, warp m16 x n64.
// smem pool: phase1 {sA,sB3} aliases phase2 {sRed}.
// ---------------------------------------------------------------------------
__global__ void __launch_bounds__(256) gemm3_mma_kernel(
    const int*   __restrict__ nbr,
    const float* __restrict__ W3,
    const float* __restrict__ b3,
    const float* __restrict__ fy,
    float*       __restrict__ out)
{
    __shared__ __align__(16) char pool[33536];
    uint32_t* sA   = (uint32_t*)pool;                       // 128*SA_P*4 = 10240
    uint32_t* sB3  = (uint32_t*)(pool + 128 * SA_P * 4);    // 16*SB3_P*4 = 4608
    float*    sRed = (float*)pool;                          // 128*65*4   = 33280
    __shared__ int s_nbr[128];

    const int tid  = threadIdx.x;
    const int e0   = blockIdx.x * 128;
    const int warp = tid >> 5, lane = tid & 31;
    const int lr = lane >> 2, lc = lane & 3;

    if (tid < 128) s_nbr[tid] = nbr[e0 + tid];

    const int ar = tid >> 1, acb = (tid & 1) * 8;
    const float* pA = g_H2 + (size_t)(e0 + ar) * 256 + acb;
    const int bk = tid >> 4, bcb = (tid & 15) * 4;

    float acc[8][4];
#pragma unroll
    for (int ni = 0; ni < 8; ni++)
#pragma unroll
        for (int t = 0; t < 4; t++) acc[ni][t] = 0.f;

    // prologue: stage chunk 0
    {
        const float4* g = (const float4*)(pA);
        float4 v0 = g[0], v1 = g[1];
        uint32_t* d = sA + ar * SA_P + acb;
        d[0] = f2tf32(v0.x); d[1] = f2tf32(v0.y); d[2] = f2tf32(v0.z); d[3] = f2tf32(v0.w);
        d[4] = f2tf32(v1.x); d[5] = f2tf32(v1.y); d[6] = f2tf32(v1.z); d[7] = f2tf32(v1.w);
        float4 w = *(const float4*)(W3 + (size_t)bk * 64 + bcb);
        uint32_t* db = sB3 + bk * SB3_P + bcb;
        db[0] = f2tf32(w.x); db[1] = f2tf32(w.y); db[2] = f2tf32(w.z); db[3] = f2tf32(w.w);
    }
    __syncthreads();

    for (int k0 = 0; k0 < 256; k0 += 16) {
        const bool nx = (k0 + 16) < 256;
        float4 v0, v1, w;
        if (nx) {
            const float4* g = (const float4*)(pA + k0 + 16);
            v0 = g[0]; v1 = g[1];
            w = *(const float4*)(W3 + (size_t)(k0 + 16 + bk) * 64 + bcb);
        }
#pragma unroll
        for (int kk = 0; kk < 16; kk += 8) {
            uint32_t afr[4];
            {
                int r = warp * 16 + lr;
                afr[0] = sA[r * SA_P + kk + lc];
                afr[1] = sA[(r + 8) * SA_P + kk + lc];
                afr[2] = sA[r * SA_P + kk + lc + 4];
                afr[3] = sA[(r + 8) * SA_P + kk + lc + 4];
            }
#pragma unroll
            for (int ni = 0; ni < 8; ni++) {
                uint32_t bfr[2];
                int nn = ni * 8 + lr;
                bfr[0] = sB3[(kk + lc) * SB3_P + nn];
                bfr[1] = sB3[(kk + 4 + lc) * SB3_P + nn];
                mma_tf32(acc[ni], afr, bfr);
            }
        }
        __syncthreads();
        if (nx) {
            uint32_t* d = sA + ar * SA_P + acb;
            d[0] = f2tf32(v0.x); d[1] = f2tf32(v0.y); d[2] = f2tf32(v0.z); d[3] = f2tf32(v0.w);
            d[4] = f2tf32(v1.x); d[5] = f2tf32(v1.y); d[6] = f2tf32(v1.z); d[7] = f2tf32(v1.w);
            uint32_t* db = sB3 + bk * SB3_P + bcb;
            db[0] = f2tf32(w.x); db[1] = f2tf32(w.y); db[2] = f2tf32(w.z); db[3] = f2tf32(w.w);
            __syncthreads();
        }
    }

    // epilogue: +b3, *f_y, stage into sRed (aliases sA/sB3 — mainloop done)
    {
        int r0 = warp * 16 + lr;
        int r1 = r0 + 8;
        int nb0 = s_nbr[r0], nb1 = s_nbr[r1];
#pragma unroll
        for (int ni = 0; ni < 8; ni++) {
            int col = ni * 8 + lc * 2;
            float bb0 = b3[col], bb1 = b3[col + 1];
            float2 f0 = *(const float2*)(fy + (size_t)nb0 * 64 + col);
            float2 f1 = *(const float2*)(fy + (size_t)nb1 * 64 + col);
            sRed[r0 * 65 + col]     = (acc[ni][0] + bb0) * f0.x;
            sRed[r0 * 65 + col + 1] = (acc[ni][1] + bb1) * f0.y;
            sRed[r1 * 65 + col]     = (acc[ni][2] + bb0) * f1.x;
            sRed[r1 * 65 + col + 1] = (acc[ni][3] + bb1) * f1.y;
        }
    }
    __syncthreads();

    for (int o = tid; o < 512; o += 256) {
        int qq = o >> 6, col = o & 63;
        float s = 0.f;
#pragma unroll
        for (int t = 0; t < 16; t++) s += sRed[(qq * 16 + t) * 65 + col];
        out[(size_t)(blockIdx.x * 8 + qq) * 64 + col] = s;
    }
}

// ---------------------------------------------------------------------------
extern "C" void kernel_launch(void* const* d_in, const int* in_sizes, int n_in,
                              void* d_out, int out_size)
{
    const float* y   = (const float*)d_in[0];
    const float* x   = (const float*)d_in[1];
    const float* f_y = (const float*)d_in[2];
    const int*   nbr = (const int*)d_in[3];
    // d_in[4] = neighbors_row_splits (uniform K=16 -> q = e>>4)
    const float* W1  = (const float*)d_in[5];
    const float* b1  = (const float*)d_in[6];
    const float* W2  = (const float*)d_in[7];
    const float* b2  = (const float*)d_in[8];
    const float* W3  = (const float*)d_in[9];
    const float* b3  = (const float*)d_in[10];
    float* out = (float*)d_out;

    embed_mma_kernel<<<(N_Y + 127) / 128, 512>>>(y, W1, nullptr, 0, N_Y);
    embed_mma_kernel<<<(N_X + 127) / 128, 512>>>(x, W1 + 192 * 256, b1, 1, N_X);
    gemm2_mma_kernel<<<NE / 128, 512>>>(nbr, W2, b2);
    gemm3_mma_kernel<<<NE / 128, 256>>>(nbr, W3, b3, f_y, out);
}

// round 4
// speedup vs baseline: 2.8396x; 1.1657x over previous
#include <cuda_runtime.h>
#include <math.h>
#include <stdint.h>

#define N_Y   100000
#define N_X   20000
#define KNN   16
#define NE    (N_X * KNN)      // 320000 edges
#define HID   256
#define CIN   64

#define SA_P 20     // A smem row pitch (words): ldmatrix conflict-free
#define PK   20     // B smem row pitch (words), [n][k] layout

// Scratch (device globals: allocation-free contract)
__device__ float    g_Ay[(size_t)N_Y * HID];
__device__ float    g_Bx[(size_t)N_X * HID];
__device__ uint32_t g_H2u[(size_t)NE * HID];       // tf32 bits
// transposed + tf32-converted weights, [n][k] dense
__device__ uint32_t g_W1aT[256 * 192];
__device__ uint32_t g_W1bT[256 * 192];
__device__ uint32_t g_W2T[256 * 256];
__device__ uint32_t g_W3T[64 * 256];

__device__ __forceinline__ float gelu_f(float v) {
    return 0.5f * v * (1.0f + erff(v * 0.70710678118654752f));
}
__device__ __forceinline__ uint32_t f2tf32(float x) {
    uint32_t r;
    asm("cvt.rna.tf32.f32 %0, %1;" : "=r"(r) : "f"(x));
    return r;
}
__device__ __forceinline__ void mma_tf32(float* d, const uint32_t* a, const uint32_t* b) {
    asm volatile(
        "mma.sync.aligned.m16n8k8.row.col.f32.tf32.tf32.f32 "
        "{%0,%1,%2,%3}, {%4,%5,%6,%7}, {%8,%9}, {%0,%1,%2,%3};\n"
        : "+f"(d[0]), "+f"(d[1]), "+f"(d[2]), "+f"(d[3])
        : "r"(a[0]), "r"(a[1]), "r"(a[2]), "r"(a[3]), "r"(b[0]), "r"(b[1]));
}
__device__ __forceinline__ void ldsm_x4(uint32_t* r, uint32_t saddr) {
    asm volatile("ldmatrix.sync.aligned.m8n8.x4.shared.b16 {%0,%1,%2,%3}, [%4];"
                 : "=r"(r[0]), "=r"(r[1]), "=r"(r[2]), "=r"(r[3]) : "r"(saddr));
}
__device__ __forceinline__ uint32_t smem_u32(const void* p) {
    return (uint32_t)__cvta_generic_to_shared(p);
}

// per-lane ldmatrix byte offsets
// A (m16k8 from [m][k], pitch SA_P): rows m0+(l&15), col kk + ((l>>4)<<2)
__device__ __forceinline__ uint32_t a_lane_off(int lane) {
    return 4u * ((lane & 15) * SA_P + ((lane >> 4) << 2));
}
// B (two n8 x k8 from [n][k], pitch PK): rows nn+(l&7)+((l>>4)<<3), col kk+(((l>>3)&1)<<2)
__device__ __forceinline__ uint32_t b_lane_off(int lane) {
    return 4u * (((lane & 7) + ((lane >> 4) << 3)) * PK + (((lane >> 3) & 1) << 2));
}

// ---------------------------------------------------------------------------
// Weight transpose + tf32 convert: src fp32 [K][N] -> dst u32 [N][K]
// ---------------------------------------------------------------------------
__device__ __forceinline__ uint32_t* sel_dst(int w) {
    return w == 0 ? g_W1aT : w == 1 ? g_W1bT : w == 2 ? g_W2T : g_W3T;
}
__global__ void transpose_cvt_kernel(const float* __restrict__ src, int K, int N, int w)
{
    __shared__ float t[32][33];
    uint32_t* dst = sel_dst(w);
    int k0 = blockIdx.y * 32, n0 = blockIdx.x * 32;
    int tx = threadIdx.x, ty = threadIdx.y;   // 32 x 8
#pragma unroll
    for (int i = 0; i < 32; i += 8)
        t[ty + i][tx] = src[(size_t)(k0 + ty + i) * N + n0 + tx];
    __syncthreads();
#pragma unroll
    for (int i = 0; i < 32; i += 8)
        dst[(size_t)(n0 + ty + i) * K + k0 + tx] = f2tf32(t[tx][ty + i]);
}

// ---------------------------------------------------------------------------
// Embed + GEMM1: dst = emb(pts) @ W (+bias).  BM=128, BN=256, K=192.
// 512 threads = 16 warps (4 m x 4 n), warp tile 32x64.
// ---------------------------------------------------------------------------
__global__ void __launch_bounds__(512) embed_mma_kernel(
    const float* __restrict__ pts,
    const float* __restrict__ bias,  // may be null
    int which, int n)                // 0: W1aT->g_Ay, 1: W1bT->g_Bx
{
    __shared__ uint32_t sA[128 * SA_P];
    __shared__ uint32_t sB[256 * PK];
    __shared__ float s_pts[128 * 3];
    __shared__ float s_freq[32];

    const uint32_t* WT = which ? g_W1bT : g_W1aT;
    float* dst = which ? g_Bx : g_Ay;
    const int tid  = threadIdx.x;
    const int row0 = blockIdx.x * 128;
    const int warp = tid >> 5, lane = tid & 31;
    const int wm = (warp & 3) * 32, wn = (warp >> 2) * 64;
    const int lr = lane >> 2, lc = lane & 3;
    const uint32_t sAu = smem_u32(sA) + a_lane_off(lane);
    const uint32_t sBu = smem_u32(sB) + b_lane_off(lane);

    if (tid < 32) s_freq[tid] = powf(10000.0f, -(float)tid / 32.0f);
    if (tid < 384) {
        int r = tid / 3, c = tid - r * 3;
        int row = row0 + r;
        s_pts[tid] = (row < n) ? pts[row * 3 + c] : 0.f;
    }
    __syncthreads();

    const int ar = tid >> 2, acb = (tid & 3) * 4;        // A: 4 elems/thread
    const int bn = tid >> 1, bkq = (tid & 1) * 8;        // B: 8 elems/thread

    auto computeA = [&](int k0, uint32_t* av) {
#pragma unroll
        for (int j = 0; j < 4; j++) {
            int e = k0 + acb + j;
            int c = e >> 6, f = (e & 63) >> 1, s = e & 1;
            float ang = s_pts[ar * 3 + c] * s_freq[f];
            av[j] = f2tf32(s ? cosf(ang) : sinf(ang));
        }
    };

    float acc[2][8][4];
#pragma unroll
    for (int mi = 0; mi < 2; mi++)
#pragma unroll
        for (int ni = 0; ni < 8; ni++)
#pragma unroll
            for (int t = 0; t < 4; t++) acc[mi][ni][t] = 0.f;

    {   // prologue: stage chunk 0
        uint32_t av[4];
        computeA(0, av);
        *(uint4*)(sA + ar * SA_P + acb) = make_uint4(av[0], av[1], av[2], av[3]);
        const uint4* g = (const uint4*)(WT + (size_t)bn * 192 + bkq);
        uint4 w0 = g[0], w1 = g[1];
        *(uint4*)(sB + bn * PK + bkq)     = w0;
        *(uint4*)(sB + bn * PK + bkq + 4) = w1;
    }
    __syncthreads();

    for (int k0 = 0; k0 < 192; k0 += 16) {
        const bool nx = (k0 + 16) < 192;
        uint32_t av[4]; uint4 w0, w1;
        if (nx) {
            computeA(k0 + 16, av);
            const uint4* g = (const uint4*)(WT + (size_t)bn * 192 + k0 + 16 + bkq);
            w0 = g[0]; w1 = g[1];
        }
#pragma unroll
        for (int kk = 0; kk < 16; kk += 8) {
            uint32_t afr[2][4], bfr[4][4];
#pragma unroll
            for (int mi = 0; mi < 2; mi++)
                ldsm_x4(afr[mi], sAu + 4u * ((wm + mi * 16) * SA_P + kk));
#pragma unroll
            for (int np = 0; np < 4; np++)
                ldsm_x4(bfr[np], sBu + 4u * ((wn + np * 16) * PK + kk));
#pragma unroll
            for (int mi = 0; mi < 2; mi++)
#pragma unroll
                for (int np = 0; np < 4; np++) {
                    mma_tf32(acc[mi][np * 2],     afr[mi], bfr[np]);
                    mma_tf32(acc[mi][np * 2 + 1], afr[mi], bfr[np] + 2);
                }
        }
        __syncthreads();
        if (nx) {
            *(uint4*)(sA + ar * SA_P + acb) = make_uint4(av[0], av[1], av[2], av[3]);
            *(uint4*)(sB + bn * PK + bkq)     = w0;
            *(uint4*)(sB + bn * PK + bkq + 4) = w1;
            __syncthreads();
        }
    }

#pragma unroll
    for (int mi = 0; mi < 2; mi++) {
        int r0 = row0 + wm + mi * 16 + lr;
        int r1 = r0 + 8;
#pragma unroll
        for (int ni = 0; ni < 8; ni++) {
            int col = wn + ni * 8 + lc * 2;
            float bb0 = bias ? bias[col]     : 0.f;
            float bb1 = bias ? bias[col + 1] : 0.f;
            if (r0 < n) {
                float2 v; v.x = acc[mi][ni][0] + bb0; v.y = acc[mi][ni][1] + bb1;
                *(float2*)(dst + (size_t)r0 * 256 + col) = v;
            }
            if (r1 < n) {
                float2 v; v.x = acc[mi][ni][2] + bb0; v.y = acc[mi][ni][3] + bb1;
                *(float2*)(dst + (size_t)r1 * 256 + col) = v;
            }
        }
    }
}

// ---------------------------------------------------------------------------
// GEMM2 (fused gather+gelu): H2u = tf32(gelu( gelu(Ay[nbr]+Bx[q]) @ W2 + b2 ))
// BM=128 edges, BN=256, K=256. 512 threads.
// ---------------------------------------------------------------------------
__global__ void __launch_bounds__(512) gemm2_mma_kernel(
    const int*   __restrict__ nbr,
    const float* __restrict__ b2)
{
    __shared__ uint32_t sA[128 * SA_P];
    __shared__ uint32_t sB[256 * PK];
    __shared__ int s_nbr[128];

    const int tid  = threadIdx.x;
    const int e0   = blockIdx.x * 128;
    const int warp = tid >> 5, lane = tid & 31;
    const int wm = (warp & 3) * 32, wn = (warp >> 2) * 64;
    const int lr = lane >> 2, lc = lane & 3;
    const uint32_t sAu = smem_u32(sA) + a_lane_off(lane);
    const uint32_t sBu = smem_u32(sB) + b_lane_off(lane);

    if (tid < 128) s_nbr[tid] = nbr[e0 + tid];
    __syncthreads();

    const int ar = tid >> 2, acb = (tid & 3) * 4;
    const float* pA = g_Ay + (size_t)s_nbr[ar] * 256 + acb;
    const float* pB = g_Bx + (size_t)((e0 + ar) >> 4) * 256 + acb;
    const int bn = tid >> 1, bkq = (tid & 1) * 8;

    float acc[2][8][4];
#pragma unroll
    for (int mi = 0; mi < 2; mi++)
#pragma unroll
        for (int ni = 0; ni < 8; ni++)
#pragma unroll
            for (int t = 0; t < 4; t++) acc[mi][ni][t] = 0.f;

    {   // prologue
        float4 a = *(const float4*)(pA);
        float4 b = *(const float4*)(pB);
        *(uint4*)(sA + ar * SA_P + acb) = make_uint4(
            f2tf32(gelu_f(a.x + b.x)), f2tf32(gelu_f(a.y + b.y)),
            f2tf32(gelu_f(a.z + b.z)), f2tf32(gelu_f(a.w + b.w)));
        const uint4* g = (const uint4*)(g_W2T + (size_t)bn * 256 + bkq);
        uint4 w0 = g[0], w1 = g[1];
        *(uint4*)(sB + bn * PK + bkq)     = w0;
        *(uint4*)(sB + bn * PK + bkq + 4) = w1;
    }
    __syncthreads();

    for (int k0 = 0; k0 < 256; k0 += 16) {
        const bool nx = (k0 + 16) < 256;
        float4 a, b; uint4 w0, w1;
        if (nx) {
            a = *(const float4*)(pA + k0 + 16);
            b = *(const float4*)(pB + k0 + 16);
            const uint4* g = (const uint4*)(g_W2T + (size_t)bn * 256 + k0 + 16 + bkq);
            w0 = g[0]; w1 = g[1];
        }
#pragma unroll
        for (int kk = 0; kk < 16; kk += 8) {
            uint32_t afr[2][4], bfr[4][4];
#pragma unroll
            for (int mi = 0; mi < 2; mi++)
                ldsm_x4(afr[mi], sAu + 4u * ((wm + mi * 16) * SA_P + kk));
#pragma unroll
            for (int np = 0; np < 4; np++)
                ldsm_x4(bfr[np], sBu + 4u * ((wn + np * 16) * PK + kk));
#pragma unroll
            for (int mi = 0; mi < 2; mi++)
#pragma unroll
                for (int np = 0; np < 4; np++) {
                    mma_tf32(acc[mi][np * 2],     afr[mi], bfr[np]);
                    mma_tf32(acc[mi][np * 2 + 1], afr[mi], bfr[np] + 2);
                }
        }
        __syncthreads();
        if (nx) {
            *(uint4*)(sA + ar * SA_P + acb) = make_uint4(
                f2tf32(gelu_f(a.x + b.x)), f2tf32(gelu_f(a.y + b.y)),
                f2tf32(gelu_f(a.z + b.z)), f2tf32(gelu_f(a.w + b.w)));
            *(uint4*)(sB + bn * PK + bkq)     = w0;
            *(uint4*)(sB + bn * PK + bkq + 4) = w1;
            __syncthreads();
        }
    }

    // epilogue: +b2, gelu, tf32-store
#pragma unroll
    for (int mi = 0; mi < 2; mi++) {
        int r0 = e0 + wm + mi * 16 + lr;
#pragma unroll
        for (int ni = 0; ni < 8; ni++) {
            int col = wn + ni * 8 + lc * 2;
            float bb0 = b2[col], bb1 = b2[col + 1];
            uint2 v0, v1;
            v0.x = f2tf32(gelu_f(acc[mi][ni][0] + bb0));
            v0.y = f2tf32(gelu_f(acc[mi][ni][1] + bb1));
            v1.x = f2tf32(gelu_f(acc[mi][ni][2] + bb0));
            v1.y = f2tf32(gelu_f(acc[mi][ni][3] + bb1));
            *(uint2*)(g_H2u + (size_t)r0 * 256 + col) = v0;
            *(uint2*)(g_H2u + (size_t)(r0 + 8) * 256 + col) = v1;
        }
    }
}

// ---------------------------------------------------------------------------
// GEMM3 + segsum: out = segsum( (H2 @ W3 + b3) * f_y[nbr] )
// BM=128 edges, BN=64, K=256. 256 threads = 8 warps, warp m16 x n64.
// ---------------------------------------------------------------------------
__global__ void __launch_bounds__(256) gemm3_mma_kernel(
    const int*   __restrict__ nbr,
    const float* __restrict__ b3,
    const float* __restrict__ fy,
    float*       __restrict__ out)
{
    __shared__ __align__(16) char pool[33536];
    uint32_t* sA   = (uint32_t*)pool;                       // 128*20*4 = 10240
    uint32_t* sB3  = (uint32_t*)(pool + 128 * SA_P * 4);    // 64*20*4  = 5120
    float*    sRed = (float*)pool;                          // 128*65*4 = 33280
    __shared__ int s_nbr[128];

    const int tid  = threadIdx.x;
    const int e0   = blockIdx.x * 128;
    const int warp = tid >> 5, lane = tid & 31;
    const int lr = lane >> 2, lc = lane & 3;
    const uint32_t sAu = smem_u32(sA) + a_lane_off(lane);
    const uint32_t sBu = smem_u32(sB3) + b_lane_off(lane);

    if (tid < 128) s_nbr[tid] = nbr[e0 + tid];

    const int ar = tid >> 1, acb = (tid & 1) * 8;
    const uint32_t* pA = g_H2u + (size_t)(e0 + ar) * 256 + acb;
    const int bn = tid >> 2, bkq = (tid & 3) * 4;   // 64 n-rows x 16 k / 256 thr

    float acc[8][4];
#pragma unroll
    for (int ni = 0; ni < 8; ni++)
#pragma unroll
        for (int t = 0; t < 4; t++) acc[ni][t] = 0.f;

    {   // prologue
        const uint4* g = (const uint4*)(pA);
        *(uint4*)(sA + ar * SA_P + acb)     = g[0];
        *(uint4*)(sA + ar * SA_P + acb + 4) = g[1];
        *(uint4*)(sB3 + bn * PK + bkq) =
            *(const uint4*)(g_W3T + (size_t)bn * 256 + bkq);
    }
    __syncthreads();

    for (int k0 = 0; k0 < 256; k0 += 16) {
        const bool nx = (k0 + 16) < 256;
        uint4 v0, v1, w;
        if (nx) {
            const uint4* g = (const uint4*)(pA + k0 + 16);
            v0 = g[0]; v1 = g[1];
            w = *(const uint4*)(g_W3T + (size_t)bn * 256 + k0 + 16 + bkq);
        }
#pragma unroll
        for (int kk = 0; kk < 16; kk += 8) {
            uint32_t afr[4], bfr[4][4];
            ldsm_x4(afr, sAu + 4u * ((warp * 16) * SA_P + kk));
#pragma unroll
            for (int np = 0; np < 4; np++)
                ldsm_x4(bfr[np], sBu + 4u * ((np * 16) * PK + kk));
#pragma unroll
            for (int np = 0; np < 4; np++) {
                mma_tf32(acc[np * 2],     afr, bfr[np]);
                mma_tf32(acc[np * 2 + 1], afr, bfr[np] + 2);
            }
        }
        __syncthreads();
        if (nx) {
            *(uint4*)(sA + ar * SA_P + acb)     = v0;
            *(uint4*)(sA + ar * SA_P + acb + 4) = v1;
            *(uint4*)(sB3 + bn * PK + bkq)      = w;
            __syncthreads();
        }
    }

    // epilogue: +b3, *f_y, stage into sRed (aliases sA/sB3)
    {
        int r0 = warp * 16 + lr;
        int r1 = r0 + 8;
        int nb0 = s_nbr[r0], nb1 = s_nbr[r1];
#pragma unroll
        for (int ni = 0; ni < 8; ni++) {
            int col = ni * 8 + lc * 2;
            float bb0 = b3[col], bb1 = b3[col + 1];
            float2 f0 = *(const float2*)(fy + (size_t)nb0 * 64 + col);
            float2 f1 = *(const float2*)(fy + (size_t)nb1 * 64 + col);
            sRed[r0 * 65 + col]     = (acc[ni][0] + bb0) * f0.x;
            sRed[r0 * 65 + col + 1] = (acc[ni][1] + bb1) * f0.y;
            sRed[r1 * 65 + col]     = (acc[ni][2] + bb0) * f1.x;
            sRed[r1 * 65 + col + 1] = (acc[ni][3] + bb1) * f1.y;
        }
    }
    __syncthreads();

    for (int o = tid; o < 512; o += 256) {
        int qq = o >> 6, col = o & 63;
        float s = 0.f;
#pragma unroll
        for (int t = 0; t < 16; t++) s += sRed[(qq * 16 + t) * 65 + col];
        out[(size_t)(blockIdx.x * 8 + qq) * 64 + col] = s;
    }
}

// ---------------------------------------------------------------------------
extern "C" void kernel_launch(void* const* d_in, const int* in_sizes, int n_in,
                              void* d_out, int out_size)
{
    const float* y   = (const float*)d_in[0];
    const float* x   = (const float*)d_in[1];
    const float* f_y = (const float*)d_in[2];
    const int*   nbr = (const int*)d_in[3];
    // d_in[4] = neighbors_row_splits (uniform K=16 -> q = e>>4)
    const float* W1  = (const float*)d_in[5];
    const float* b1  = (const float*)d_in[6];
    const float* W2  = (const float*)d_in[7];
    const float* b2  = (const float*)d_in[8];
    const float* W3  = (const float*)d_in[9];
    const float* b3  = (const float*)d_in[10];
    float* out = (float*)d_out;

    dim3 tb(32, 8);
    transpose_cvt_kernel<<<dim3(8, 6), tb>>>(W1,             192, 256, 0);
    transpose_cvt_kernel<<<dim3(8, 6), tb>>>(W1 + 192 * 256, 192, 256, 1);
    transpose_cvt_kernel<<<dim3(8, 8), tb>>>(W2,             256, 256, 2);
    transpose_cvt_kernel<<<dim3(2, 8), tb>>>(W3,             256,  64, 3);

    embed_mma_kernel<<<(N_Y + 127) / 128, 512>>>(y, nullptr, 0, N_Y);
    embed_mma_kernel<<<(N_X + 127) / 128, 512>>>(x, b1, 1, N_X);
    gemm2_mma_kernel<<<NE / 128, 512>>>(nbr, b2);
    gemm3_mma_kernel<<<NE / 128, 256>>>(nbr, b3, f_y, out);
}